// round 5
// baseline (speedup 1.0000x reference)
#include <cuda_runtime.h>
#include <cstdint>

// Problem constants (fixed shapes from reference setup_inputs)
#define B_   2
#define T_   12
#define N_   10000
#define CG   16        // graph channels
#define CI   8         // grid channels
#define Hh   128
#define Ww   128
#define HW   16384
#define F_   64
#define FH   32        // F/2
#define NPIX (B_*T_*HW)        // 393216
#define TILE 256               // pixels per block tile
#define SMS  260               // smem row stride (keeps 16B alignment: 260*4=1040)
#define NTILES (NPIX/TILE)     // 1536
#define BN_EPS 1e-5f

// Scratch (no cudaMalloc allowed)
__device__ __align__(128) float g_interp[(size_t)B_*T_*HW*CG]; // [b,t,hw,c] ~25MB
__device__ float g_sum[F_];
__device__ float g_sumsq[F_];
__device__ float g_scale[F_];
__device__ float g_shift[F_];

// ---- packed f32x2 helpers (Blackwell dual-FP32 pipe) ----
#define PACK2(d, lo, hi)  asm("mov.b64 %0, {%1, %2};" : "=l"(d) : "f"(lo), "f"(hi))
#define UNPACK2(lo, hi, s) asm("mov.b64 {%0, %1}, %2;" : "=f"(lo), "=f"(hi) : "l"(s))
#define FMA2(d, a, b, c)  asm("fma.rn.f32x2 %0, %1, %2, %3;" : "=l"(d) : "l"(a), "l"(b), "l"(c))
#define ADD2(d, a, b)     asm("add.rn.f32x2 %0, %1, %2;"     : "=l"(d) : "l"(a), "l"(b))

// K0: zero interp scratch + stat accumulators
__global__ void k_zero() {
    const size_t n4 = ((size_t)B_*T_*HW*CG) / 4;
    float4* p = (float4*)g_interp;
    const float4 z = make_float4(0.f, 0.f, 0.f, 0.f);
    for (size_t i = (size_t)blockIdx.x * blockDim.x + threadIdx.x; i < n4;
         i += (size_t)gridDim.x * blockDim.x)
        p[i] = z;
    if (blockIdx.x == 0 && threadIdx.x < F_) {
        g_sum[threadIdx.x] = 0.f;
        g_sumsq[threadIdx.x] = 0.f;
    }
}

// K1: scatter-add graph_data -> g_interp  (thread = (b, n, c))
__global__ void k_scatter(const float* __restrict__ graph,
                          const float* __restrict__ coords) {
    int idx = blockIdx.x * blockDim.x + threadIdx.x;
    if (idx >= B_ * N_ * CG) return;
    int c = idx & (CG - 1);
    int node = idx >> 4;
    int b = node / N_;
    int n = node - b * N_;

    float la = coords[(b * N_ + n) * 2 + 0];
    float lo = coords[(b * N_ + n) * 2 + 1];
    int lat = (int)(la * (float)Hh);           // trunc, matches astype(int32)
    int lon = (int)(lo * (float)Ww);
    lat = min(max(lat, 0), Hh - 1);
    lon = min(max(lon, 0), Ww - 1);
    int pos = lat * Ww + lon;

#pragma unroll
    for (int t = 0; t < T_; t++) {
        float v = graph[((b * T_ + t) * N_ + n) * CG + c];
        atomicAdd(&g_interp[((b * T_ + t) * HW + pos) * CG + c], v);
    }
}

// K2: fused projection kernel.
// STATS=true : accumulate per-channel sum / sumsq into g_sum/g_sumsq
// STATS=false: apply precomputed scale/shift and write output [B,T,F,H,W]
// Layout: warp lane owns channels f=lane (graph side) and f=lane+32 (grid side).
// Inputs staged transposed in smem [c][pixel]; uniform LDS.128 feeds packed
// f32x2 FMAs over pixel pairs.
template<bool STATS>
__global__ void __launch_bounds__(256, 2) k_main(
    const float* __restrict__ grid_data,
    const float* __restrict__ Wg, const float* __restrict__ bg,
    const float* __restrict__ Wr, const float* __restrict__ br,
    float* __restrict__ out)
{
    __shared__ float s_in[24 * SMS];
    __shared__ float s_sum[F_], s_sq[F_];

    const int tid  = threadIdx.x;
    const int lane = tid & 31;
    const int warp = tid >> 5;
    const int P0   = blockIdx.x * TILE;   // tile never crosses a bt boundary
    const int bt   = P0 / HW;
    const int hw0  = P0 - bt * HW;

    if (STATS && tid < F_) { s_sum[tid] = 0.f; s_sq[tid] = 0.f; }

    // stage interp [pixel][c] -> s_in[c][pixel]  (256 px * 16 ch)
#pragma unroll
    for (int k = 0; k < 4; k++) {
        int q = tid + k * 256;                  // 0..1023 float4s
        float4 v = *(const float4*)&g_interp[(size_t)P0 * CG + q * 4];
        int pixel = q >> 2;
        int cq = (q & 3) * 4;
        s_in[(cq + 0) * SMS + pixel] = v.x;
        s_in[(cq + 1) * SMS + pixel] = v.y;
        s_in[(cq + 2) * SMS + pixel] = v.z;
        s_in[(cq + 3) * SMS + pixel] = v.w;
    }
    // stage grid_data (already channel-major) -> s_in[16+c][pixel]
#pragma unroll
    for (int k = 0; k < 2; k++) {
        int qq = tid + k * 256;                 // 512 float4s
        int c = qq >> 6;
        int p4 = (qq & 63) * 4;
        float4 v = *(const float4*)&grid_data[(size_t)(bt * CI + c) * HW + hw0 + p4];
        *(float4*)&s_in[(16 + c) * SMS + p4] = v;
    }
    __syncthreads();

    // per-lane weights, duplicated into packed pairs
    unsigned long long wg2[CG], wr2[CI], bg2, br2;
#pragma unroll
    for (int c = 0; c < CG; c++) { float w = Wg[c * FH + lane]; PACK2(wg2[c], w, w); }
#pragma unroll
    for (int c = 0; c < CI; c++) { float w = Wr[c * FH + lane]; PACK2(wr2[c], w, w); }
    { float x = bg[lane]; PACK2(bg2, x, x); }
    { float x = br[lane]; PACK2(br2, x, x); }

    unsigned long long sc_g2 = 0, sh_g2 = 0, sc_r2 = 0, sh_r2 = 0;
    if (!STATS) {
        float s = g_scale[lane],      h = g_shift[lane];
        PACK2(sc_g2, s, s); PACK2(sh_g2, h, h);
        s = g_scale[lane + 32];       h = g_shift[lane + 32];
        PACK2(sc_r2, s, s); PACK2(sh_r2, h, h);
    }

    unsigned long long sum_g = 0, sq_g = 0, sum_r = 0, sq_r = 0; // packed (0,0)

    const int pbase = warp * 32;    // this warp's 32 pixels in the tile
#pragma unroll
    for (int g = 0; g < 8; g++) {
        const int p = pbase + g * 4;
        unsigned long long accg01 = bg2, accg23 = bg2;
        unsigned long long accr01 = br2, accr23 = br2;

#pragma unroll
        for (int c = 0; c < CG; c++) {
            float4 v = *(const float4*)&s_in[c * SMS + p];  // uniform -> broadcast
            unsigned long long a01, a23;
            PACK2(a01, v.x, v.y); PACK2(a23, v.z, v.w);
            FMA2(accg01, a01, wg2[c], accg01);
            FMA2(accg23, a23, wg2[c], accg23);
        }
#pragma unroll
        for (int c = 0; c < CI; c++) {
            float4 v = *(const float4*)&s_in[(16 + c) * SMS + p];
            unsigned long long a01, a23;
            PACK2(a01, v.x, v.y); PACK2(a23, v.z, v.w);
            FMA2(accr01, a01, wr2[c], accr01);
            FMA2(accr23, a23, wr2[c], accr23);
        }

        if (STATS) {
            ADD2(sum_g, sum_g, accg01); ADD2(sum_g, sum_g, accg23);
            FMA2(sq_g, accg01, accg01, sq_g); FMA2(sq_g, accg23, accg23, sq_g);
            ADD2(sum_r, sum_r, accr01); ADD2(sum_r, sum_r, accr23);
            FMA2(sq_r, accr01, accr01, sq_r); FMA2(sq_r, accr23, accr23, sq_r);
        } else {
            FMA2(accg01, accg01, sc_g2, sh_g2);
            FMA2(accg23, accg23, sc_g2, sh_g2);
            FMA2(accr01, accr01, sc_r2, sh_r2);
            FMA2(accr23, accr23, sc_r2, sh_r2);
            float4 o;
            UNPACK2(o.x, o.y, accg01); UNPACK2(o.z, o.w, accg23);
            *(float4*)&out[(size_t)(bt * F_ + lane) * HW + hw0 + p] = o;
            UNPACK2(o.x, o.y, accr01); UNPACK2(o.z, o.w, accr23);
            *(float4*)&out[(size_t)(bt * F_ + 32 + lane) * HW + hw0 + p] = o;
        }
    }

    if (STATS) {
        float lo, hi, a;
        UNPACK2(lo, hi, sum_g); a = lo + hi; atomicAdd(&s_sum[lane], a);
        UNPACK2(lo, hi, sq_g);  a = lo + hi; atomicAdd(&s_sq[lane], a);
        UNPACK2(lo, hi, sum_r); a = lo + hi; atomicAdd(&s_sum[lane + 32], a);
        UNPACK2(lo, hi, sq_r);  a = lo + hi; atomicAdd(&s_sq[lane + 32], a);
        __syncthreads();
        if (tid < F_) {
            atomicAdd(&g_sum[tid],   s_sum[tid]);
            atomicAdd(&g_sumsq[tid], s_sq[tid]);
        }
    }
}

// K3: finalize BN stats -> per-channel affine (scale, shift)
__global__ void k_finalize(const float* __restrict__ gamma,
                           const float* __restrict__ beta) {
    int f = threadIdx.x;
    if (f >= F_) return;
    const float inv = 1.0f / (float)NPIX;
    float mean = g_sum[f] * inv;
    float var  = g_sumsq[f] * inv - mean * mean;   // biased var (ddof=0)
    float sc   = gamma[f] * rsqrtf(var + BN_EPS);
    g_scale[f] = sc;
    g_shift[f] = beta[f] - mean * sc;
}

extern "C" void kernel_launch(void* const* d_in, const int* in_sizes, int n_in,
                              void* d_out, int out_size) {
    (void)in_sizes; (void)n_in; (void)out_size;
    const float* graph  = (const float*)d_in[0];   // [B,T,N,16]
    const float* grid   = (const float*)d_in[1];   // [B,T,8,H,W]
    const float* coords = (const float*)d_in[2];   // [B,N,2]
    // d_in[3], d_in[4]: time indices — unused by reference
    const float* Wg     = (const float*)d_in[5];   // [16,32]
    const float* bg     = (const float*)d_in[6];   // [32]
    const float* Wr     = (const float*)d_in[7];   // [8,32]
    const float* br     = (const float*)d_in[8];   // [32]
    const float* gamma  = (const float*)d_in[9];   // [64]
    const float* beta   = (const float*)d_in[10];  // [64]
    float* out = (float*)d_out;                    // [B,T,64,H,W]

    k_zero<<<1024, 256>>>();
    k_scatter<<<(B_ * N_ * CG + 255) / 256, 256>>>(graph, coords);
    k_main<true><<<NTILES, 256>>>(grid, Wg, bg, Wr, br, out);
    k_finalize<<<1, 64>>>(gamma, beta);
    k_main<false><<<NTILES, 256>>>(grid, Wg, bg, Wr, br, out);
}

// round 6
// speedup vs baseline: 1.2778x; 1.2778x over previous
#include <cuda_runtime.h>
#include <cstdint>

// Fixed shapes
#define B_   2
#define T_   12
#define N_   10000
#define CG   16
#define CI   8
#define Hh   128
#define Ww   128
#define HW   16384
#define F_   64
#define FH   32
#define NPIX (B_*T_*HW)        // 393216
#define TILE 256
#define SMS  260               // smem row stride (words); mult of 4 -> 16B aligned rows
#define NTILES (NPIX/TILE)     // 1536
#define BN_EPS 1e-5f

typedef unsigned long long ull;

// Scratch (no cudaMalloc allowed)
__device__ __align__(128) float g_interp[(size_t)B_*T_*HW*CG]; // [b,t,hw,c] ~25MB
__device__ float g_sum[F_];
__device__ float g_sumsq[F_];

#define PACK2(d, lo, hi)   asm("mov.b64 %0, {%1, %2};" : "=l"(d) : "f"(lo), "f"(hi))
#define UNPACK2(lo, hi, s) asm("mov.b64 {%0, %1}, %2;" : "=f"(lo), "=f"(hi) : "l"(s))
#define FMA2(d, a, b, c)   asm("fma.rn.f32x2 %0, %1, %2, %3;" : "=l"(d) : "l"(a), "l"(b), "l"(c))
#define ADD2(d, a, b)      asm("add.rn.f32x2 %0, %1, %2;"     : "=l"(d) : "l"(a), "l"(b))

// ---------------------------------------------------------------- K0: zero
__global__ void k_zero() {
    const size_t n4 = ((size_t)B_*T_*HW*CG) / 4;
    float4* p = (float4*)g_interp;
    const float4 z = make_float4(0.f, 0.f, 0.f, 0.f);
    for (size_t i = (size_t)blockIdx.x * blockDim.x + threadIdx.x; i < n4;
         i += (size_t)gridDim.x * blockDim.x)
        p[i] = z;
    if (blockIdx.x == 0 && threadIdx.x < F_) {
        g_sum[threadIdx.x] = 0.f;
        g_sumsq[threadIdx.x] = 0.f;
    }
}

// ------------------------------------------------------------- K1: scatter
__global__ void k_scatter(const float* __restrict__ graph,
                          const float* __restrict__ coords) {
    int idx = blockIdx.x * blockDim.x + threadIdx.x;
    if (idx >= B_ * N_ * CG) return;
    int c = idx & (CG - 1);
    int node = idx >> 4;
    int b = node / N_;
    int n = node - b * N_;

    float la = coords[(b * N_ + n) * 2 + 0];
    float lo = coords[(b * N_ + n) * 2 + 1];
    int lat = (int)(la * (float)Hh);
    int lon = (int)(lo * (float)Ww);
    lat = min(max(lat, 0), Hh - 1);
    lon = min(max(lon, 0), Ww - 1);
    int pos = lat * Ww + lon;

#pragma unroll
    for (int t = 0; t < T_; t++) {
        float v = graph[((b * T_ + t) * N_ + n) * CG + c];
        atomicAdd(&g_interp[((b * T_ + t) * HW + pos) * CG + c], v);
    }
}

// --------------------------------------------------------------- K2: stats
// lane = channel f (graph side f=lane, grid side f=lane+32). Inputs staged
// transposed [c][px] in smem; pixel-pairs read directly as packed ulonglong2
// (no mov packing). Accumulates per-channel sum / sumsq of x = proj + bias.
__global__ void __launch_bounds__(256) k_stats(
    const float* __restrict__ grid_data,
    const float* __restrict__ Wg, const float* __restrict__ bg,
    const float* __restrict__ Wr, const float* __restrict__ br)
{
    __shared__ float s_in[24 * SMS];
    __shared__ float s_sum[F_], s_sq[F_];

    const int tid  = threadIdx.x;
    const int lane = tid & 31;
    const int warp = tid >> 5;
    const int P0   = blockIdx.x * TILE;
    const int bt   = P0 / HW;
    const int hw0  = P0 - bt * HW;

    if (tid < F_) { s_sum[tid] = 0.f; s_sq[tid] = 0.f; }

    // interp [px][c] -> s_in[c][px]
#pragma unroll
    for (int k = 0; k < 4; k++) {
        int q = tid + k * 256;
        float4 v = *(const float4*)&g_interp[(size_t)P0 * CG + q * 4];
        int pixel = q >> 2;
        int cq = (q & 3) * 4;
        s_in[(cq + 0) * SMS + pixel] = v.x;
        s_in[(cq + 1) * SMS + pixel] = v.y;
        s_in[(cq + 2) * SMS + pixel] = v.z;
        s_in[(cq + 3) * SMS + pixel] = v.w;
    }
    // grid_data (channel-major) -> s_in[16+c][px]
#pragma unroll
    for (int k = 0; k < 2; k++) {
        int qq = tid + k * 256;
        int c = qq >> 6;
        int p4 = (qq & 63) * 4;
        float4 v = *(const float4*)&grid_data[(size_t)(bt * CI + c) * HW + hw0 + p4];
        *(float4*)&s_in[(16 + c) * SMS + p4] = v;
    }
    __syncthreads();

    // per-lane duplicated packed weights (registers)
    ull wg2[CG], wr2[CI], bg2, br2;
#pragma unroll
    for (int c = 0; c < CG; c++) { float w = Wg[c * FH + lane]; PACK2(wg2[c], w, w); }
#pragma unroll
    for (int c = 0; c < CI; c++) { float w = Wr[c * FH + lane]; PACK2(wr2[c], w, w); }
    { float x = bg[lane]; PACK2(bg2, x, x); }
    { float x = br[lane]; PACK2(br2, x, x); }

    ull sum_g = 0, sq_g = 0, sum_r = 0, sq_r = 0;

    const int pbase = warp * 32;
#pragma unroll
    for (int g = 0; g < 8; g++) {
        const int p = pbase + g * 4;
        ull accg01 = bg2, accg23 = bg2;
        ull accr01 = br2, accr23 = br2;

#pragma unroll
        for (int c = 0; c < CG; c++) {
            ulonglong2 u = *(const ulonglong2*)&s_in[c * SMS + p]; // (p,p+1),(p+2,p+3)
            FMA2(accg01, u.x, wg2[c], accg01);
            FMA2(accg23, u.y, wg2[c], accg23);
        }
#pragma unroll
        for (int c = 0; c < CI; c++) {
            ulonglong2 u = *(const ulonglong2*)&s_in[(16 + c) * SMS + p];
            FMA2(accr01, u.x, wr2[c], accr01);
            FMA2(accr23, u.y, wr2[c], accr23);
        }

        ADD2(sum_g, sum_g, accg01); ADD2(sum_g, sum_g, accg23);
        FMA2(sq_g, accg01, accg01, sq_g); FMA2(sq_g, accg23, accg23, sq_g);
        ADD2(sum_r, sum_r, accr01); ADD2(sum_r, sum_r, accr23);
        FMA2(sq_r, accr01, accr01, sq_r); FMA2(sq_r, accr23, accr23, sq_r);
    }

    float lo, hi, a;
    UNPACK2(lo, hi, sum_g); a = lo + hi; atomicAdd(&s_sum[lane], a);
    UNPACK2(lo, hi, sq_g);  a = lo + hi; atomicAdd(&s_sq[lane], a);
    UNPACK2(lo, hi, sum_r); a = lo + hi; atomicAdd(&s_sum[lane + 32], a);
    UNPACK2(lo, hi, sq_r);  a = lo + hi; atomicAdd(&s_sq[lane + 32], a);
    __syncthreads();
    if (tid < F_) {
        atomicAdd(&g_sum[tid],   s_sum[tid]);
        atomicAdd(&g_sumsq[tid], s_sq[tid]);
    }
}

// ----------------------------------------------------------- K3: normalize
// lane = pixel. Per-block prologue computes BN affine from g_sum/g_sumsq
// (finalize folded in), folds scale into packed pair-weights in smem.
// Output stores are fully coalesced STG.32 (128B/warp).
__global__ void __launch_bounds__(256) k_norm(
    const float* __restrict__ grid_data,
    const float* __restrict__ Wg, const float* __restrict__ bg,
    const float* __restrict__ Wr, const float* __restrict__ br,
    const float* __restrict__ gamma, const float* __restrict__ beta,
    float* __restrict__ out)
{
    __shared__ float s_sc[F_], s_sh[F_];
    __shared__ __align__(16) ull s_wg[16][16];  // [j][c]: (Wg[c][2j]*sc, Wg[c][2j+1]*sc)
    __shared__ __align__(16) ull s_wr[16][8];
    __shared__ ull s_fsg[16], s_fsr[16];        // fused shift pairs

    const int tid = threadIdx.x;

    if (tid < F_) {
        const float inv = 1.0f / (float)NPIX;
        float mean = g_sum[tid] * inv;
        float var  = g_sumsq[tid] * inv - mean * mean;
        float sc   = gamma[tid] * rsqrtf(var + BN_EPS);
        s_sc[tid] = sc;
        s_sh[tid] = beta[tid] - mean * sc;
    }
    __syncthreads();

    {   // pack scale-folded weights
        int j = tid >> 4, c = tid & 15;                       // 256 graph entries
        float w0 = Wg[c * FH + 2 * j]     * s_sc[2 * j];
        float w1 = Wg[c * FH + 2 * j + 1] * s_sc[2 * j + 1];
        PACK2(s_wg[j][c], w0, w1);
        if (tid < 128) {                                      // 128 grid entries
            int jr = tid >> 3, cr = tid & 7;
            float v0 = Wr[cr * FH + 2 * jr]     * s_sc[32 + 2 * jr];
            float v1 = Wr[cr * FH + 2 * jr + 1] * s_sc[33 + 2 * jr];
            PACK2(s_wr[jr][cr], v0, v1);
        }
        if (tid < 16) {
            float f0 = bg[2 * tid]     * s_sc[2 * tid]     + s_sh[2 * tid];
            float f1 = bg[2 * tid + 1] * s_sc[2 * tid + 1] + s_sh[2 * tid + 1];
            PACK2(s_fsg[tid], f0, f1);
            float r0 = br[2 * tid]     * s_sc[32 + 2 * tid] + s_sh[32 + 2 * tid];
            float r1 = br[2 * tid + 1] * s_sc[33 + 2 * tid] + s_sh[33 + 2 * tid];
            PACK2(s_fsr[tid], r0, r1);
        }
    }
    __syncthreads();

    const int P  = blockIdx.x * TILE + tid;   // global pixel
    const int bt = P >> 14;
    const int hw = P & (HW - 1);

    // load this pixel's 24 input channels, duplicated-packed
    ull a2[CG], g2[CI];
    {
        const float4* ip = (const float4*)&g_interp[(size_t)P * CG];
#pragma unroll
        for (int k = 0; k < 4; k++) {
            float4 v = ip[k];
            PACK2(a2[4 * k + 0], v.x, v.x);
            PACK2(a2[4 * k + 1], v.y, v.y);
            PACK2(a2[4 * k + 2], v.z, v.z);
            PACK2(a2[4 * k + 3], v.w, v.w);
        }
#pragma unroll
        for (int c = 0; c < CI; c++) {
            float v = grid_data[(size_t)(bt * CI + c) * HW + hw];
            PACK2(g2[c], v, v);
        }
    }

    float* outp = out + (size_t)bt * F_ * HW + hw;

#pragma unroll
    for (int j = 0; j < 16; j++) {            // graph channels 2j, 2j+1
        ull acc = s_fsg[j];
#pragma unroll
        for (int cc = 0; cc < 8; cc++) {
            ulonglong2 w = *(const ulonglong2*)&s_wg[j][2 * cc];
            FMA2(acc, a2[2 * cc],     w.x, acc);
            FMA2(acc, a2[2 * cc + 1], w.y, acc);
        }
        float lo, hi; UNPACK2(lo, hi, acc);
        outp[(size_t)(2 * j)     * HW] = lo;   // coalesced across warp
        outp[(size_t)(2 * j + 1) * HW] = hi;
    }
#pragma unroll
    for (int j = 0; j < 16; j++) {            // grid channels 32+2j, 33+2j
        ull acc = s_fsr[j];
#pragma unroll
        for (int cc = 0; cc < 4; cc++) {
            ulonglong2 w = *(const ulonglong2*)&s_wr[j][2 * cc];
            FMA2(acc, g2[2 * cc],     w.x, acc);
            FMA2(acc, g2[2 * cc + 1], w.y, acc);
        }
        float lo, hi; UNPACK2(lo, hi, acc);
        outp[(size_t)(32 + 2 * j) * HW] = lo;
        outp[(size_t)(33 + 2 * j) * HW] = hi;
    }
}

extern "C" void kernel_launch(void* const* d_in, const int* in_sizes, int n_in,
                              void* d_out, int out_size) {
    (void)in_sizes; (void)n_in; (void)out_size;
    const float* graph  = (const float*)d_in[0];
    const float* grid   = (const float*)d_in[1];
    const float* coords = (const float*)d_in[2];
    const float* Wg     = (const float*)d_in[5];
    const float* bg     = (const float*)d_in[6];
    const float* Wr     = (const float*)d_in[7];
    const float* br     = (const float*)d_in[8];
    const float* gamma  = (const float*)d_in[9];
    const float* beta   = (const float*)d_in[10];
    float* out = (float*)d_out;

    k_zero<<<1024, 256>>>();
    k_scatter<<<(B_ * N_ * CG + 255) / 256, 256>>>(graph, coords);
    k_stats<<<NTILES, 256>>>(grid, Wg, bg, Wr, br);
    k_norm<<<NTILES, 256>>>(grid, Wg, bg, Wr, br, gamma, beta, out);
}

// round 7
// speedup vs baseline: 1.4375x; 1.1250x over previous
#include <cuda_runtime.h>
#include <cstdint>

// Fixed shapes
#define B_   2
#define T_   12
#define N_   10000
#define CG   16
#define CI   8
#define Hh   128
#define Ww   128
#define HW   16384
#define F_   64
#define FH   32
#define NPIX (B_*T_*HW)        // 393216
#define TILE 256               // stats tile (pixels per block)
#define SMS  260               // stats smem row stride (words)
#define NSTAT (NPIX/TILE)      // 1536
#define PXT  4                 // k_norm pixels per thread
#define NORM_TPB 256
#define NORM_TILE (NORM_TPB*PXT)       // 1024 px per block
#define NNORM (NPIX/NORM_TILE)         // 384
#define BN_EPS 1e-5f

typedef unsigned long long ull;

// Scratch (no cudaMalloc allowed)
__device__ __align__(128) float g_interp[(size_t)B_*T_*HW*CG]; // [b,t,hw,c] ~25MB
__device__ float g_sum[F_];
__device__ float g_sumsq[F_];

#define PACK2(d, lo, hi)   asm("mov.b64 %0, {%1, %2};" : "=l"(d) : "f"(lo), "f"(hi))
#define UNPACK2(lo, hi, s) asm("mov.b64 {%0, %1}, %2;" : "=f"(lo), "=f"(hi) : "l"(s))
#define FMA2(d, a, b, c)   asm("fma.rn.f32x2 %0, %1, %2, %3;" : "=l"(d) : "l"(a), "l"(b), "l"(c))
#define ADD2(d, a, b)      asm("add.rn.f32x2 %0, %1, %2;"     : "=l"(d) : "l"(a), "l"(b))

// ---------------------------------------------------------------- K0: zero
__global__ void k_zero() {
    const size_t n4 = ((size_t)B_*T_*HW*CG) / 4;
    float4* p = (float4*)g_interp;
    const float4 z = make_float4(0.f, 0.f, 0.f, 0.f);
    for (size_t i = (size_t)blockIdx.x * blockDim.x + threadIdx.x; i < n4;
         i += (size_t)gridDim.x * blockDim.x)
        p[i] = z;
    if (blockIdx.x == 0 && threadIdx.x < F_) {
        g_sum[threadIdx.x] = 0.f;
        g_sumsq[threadIdx.x] = 0.f;
    }
}

// ------------------------------------------------------------- K1: scatter
__global__ void k_scatter(const float* __restrict__ graph,
                          const float* __restrict__ coords) {
    int idx = blockIdx.x * blockDim.x + threadIdx.x;
    if (idx >= B_ * N_ * CG) return;
    int c = idx & (CG - 1);
    int node = idx >> 4;
    int b = node / N_;
    int n = node - b * N_;

    float la = coords[(b * N_ + n) * 2 + 0];
    float lo = coords[(b * N_ + n) * 2 + 1];
    int lat = (int)(la * (float)Hh);
    int lon = (int)(lo * (float)Ww);
    lat = min(max(lat, 0), Hh - 1);
    lon = min(max(lon, 0), Ww - 1);
    int pos = lat * Ww + lon;

#pragma unroll
    for (int t = 0; t < T_; t++) {
        float v = graph[((b * T_ + t) * N_ + n) * CG + c];
        atomicAdd(&g_interp[((b * T_ + t) * HW + pos) * CG + c], v);
    }
}

// --------------------------------------------------------------- K2: stats
// lane = channel f (graph f=lane, grid f=lane+32). Inputs staged transposed
// [c][px] in smem; pixel-pairs read as packed ulonglong2. Accumulates
// per-channel sum / sumsq of x = proj + bias into g_sum / g_sumsq.
__global__ void __launch_bounds__(256) k_stats(
    const float* __restrict__ grid_data,
    const float* __restrict__ Wg, const float* __restrict__ bg,
    const float* __restrict__ Wr, const float* __restrict__ br)
{
    __shared__ float s_in[24 * SMS];
    __shared__ float s_sum[F_], s_sq[F_];

    const int tid  = threadIdx.x;
    const int lane = tid & 31;
    const int warp = tid >> 5;
    const int P0   = blockIdx.x * TILE;
    const int bt   = P0 / HW;
    const int hw0  = P0 - bt * HW;

    if (tid < F_) { s_sum[tid] = 0.f; s_sq[tid] = 0.f; }

#pragma unroll
    for (int k = 0; k < 4; k++) {
        int q = tid + k * 256;
        float4 v = *(const float4*)&g_interp[(size_t)P0 * CG + q * 4];
        int pixel = q >> 2;
        int cq = (q & 3) * 4;
        s_in[(cq + 0) * SMS + pixel] = v.x;
        s_in[(cq + 1) * SMS + pixel] = v.y;
        s_in[(cq + 2) * SMS + pixel] = v.z;
        s_in[(cq + 3) * SMS + pixel] = v.w;
    }
#pragma unroll
    for (int k = 0; k < 2; k++) {
        int qq = tid + k * 256;
        int c = qq >> 6;
        int p4 = (qq & 63) * 4;
        float4 v = *(const float4*)&grid_data[(size_t)(bt * CI + c) * HW + hw0 + p4];
        *(float4*)&s_in[(16 + c) * SMS + p4] = v;
    }
    __syncthreads();

    ull wg2[CG], wr2[CI], bg2, br2;
#pragma unroll
    for (int c = 0; c < CG; c++) { float w = Wg[c * FH + lane]; PACK2(wg2[c], w, w); }
#pragma unroll
    for (int c = 0; c < CI; c++) { float w = Wr[c * FH + lane]; PACK2(wr2[c], w, w); }
    { float x = bg[lane]; PACK2(bg2, x, x); }
    { float x = br[lane]; PACK2(br2, x, x); }

    ull sum_g = 0, sq_g = 0, sum_r = 0, sq_r = 0;

    const int pbase = warp * 32;
#pragma unroll
    for (int g = 0; g < 8; g++) {
        const int p = pbase + g * 4;
        ull accg01 = bg2, accg23 = bg2;
        ull accr01 = br2, accr23 = br2;

#pragma unroll
        for (int c = 0; c < CG; c++) {
            ulonglong2 u = *(const ulonglong2*)&s_in[c * SMS + p];
            FMA2(accg01, u.x, wg2[c], accg01);
            FMA2(accg23, u.y, wg2[c], accg23);
        }
#pragma unroll
        for (int c = 0; c < CI; c++) {
            ulonglong2 u = *(const ulonglong2*)&s_in[(16 + c) * SMS + p];
            FMA2(accr01, u.x, wr2[c], accr01);
            FMA2(accr23, u.y, wr2[c], accr23);
        }

        ADD2(sum_g, sum_g, accg01); ADD2(sum_g, sum_g, accg23);
        FMA2(sq_g, accg01, accg01, sq_g); FMA2(sq_g, accg23, accg23, sq_g);
        ADD2(sum_r, sum_r, accr01); ADD2(sum_r, sum_r, accr23);
        FMA2(sq_r, accr01, accr01, sq_r); FMA2(sq_r, accr23, accr23, sq_r);
    }

    float lo, hi, a;
    UNPACK2(lo, hi, sum_g); a = lo + hi; atomicAdd(&s_sum[lane], a);
    UNPACK2(lo, hi, sq_g);  a = lo + hi; atomicAdd(&s_sq[lane], a);
    UNPACK2(lo, hi, sum_r); a = lo + hi; atomicAdd(&s_sum[lane + 32], a);
    UNPACK2(lo, hi, sq_r);  a = lo + hi; atomicAdd(&s_sq[lane + 32], a);
    __syncthreads();
    if (tid < F_) {
        atomicAdd(&g_sum[tid],   s_sum[tid]);
        atomicAdd(&g_sumsq[tid], s_sq[tid]);
    }
}

// ----------------------------------------------------------- K3: normalize
// Thread owns 4 consecutive pixels. Inputs held as duplicated f32x2 pairs
// (px0,px1)/(px2,px3) in registers; scale-folded dup-packed weights read
// from smem ONCE per 4 pixels (4x fewer LDS than 1px/thread); one STG.128
// per channel per 4px (4x fewer store instructions). Fully coalesced.
__global__ void __launch_bounds__(NORM_TPB, 2) k_norm(
    const float* __restrict__ grid_data,
    const float* __restrict__ Wg, const float* __restrict__ bg,
    const float* __restrict__ Wr, const float* __restrict__ br,
    const float* __restrict__ gamma, const float* __restrict__ beta,
    float* __restrict__ out)
{
    __shared__ float s_sc[F_], s_sh[F_];
    __shared__ __align__(16) ull s_wg[32 * 16]; // [f][c] dup-packed, scale-folded
    __shared__ __align__(16) ull s_wr[32 * 8];
    __shared__ ull s_fg[32], s_fr[32];          // fused bias+shift, dup-packed

    const int tid = threadIdx.x;

    if (tid < F_) {
        const float inv = 1.0f / (float)NPIX;
        float mean = g_sum[tid] * inv;
        float var  = g_sumsq[tid] * inv - mean * mean;
        float sc   = gamma[tid] * rsqrtf(var + BN_EPS);
        s_sc[tid] = sc;
        s_sh[tid] = beta[tid] - mean * sc;
    }
    __syncthreads();

    {
#pragma unroll
        for (int k = 0; k < 2; k++) {            // 512 graph weight entries
            int e = tid + k * 256;
            int f = e >> 4, c = e & 15;
            float w = Wg[c * FH + f] * s_sc[f];
            PACK2(s_wg[e], w, w);
        }
        {                                         // 256 grid weight entries
            int f = tid >> 3, c = tid & 7;
            float w = Wr[c * FH + f] * s_sc[32 + f];
            PACK2(s_wr[tid], w, w);
        }
        if (tid < 32) {
            float v = bg[tid] * s_sc[tid] + s_sh[tid];
            PACK2(s_fg[tid], v, v);
        } else if (tid < 64) {
            int f = tid - 32;
            float v = br[f] * s_sc[32 + f] + s_sh[32 + f];
            PACK2(s_fr[f], v, v);
        }
    }
    __syncthreads();

    const int P  = blockIdx.x * NORM_TILE + tid * PXT;   // first of 4 pixels
    const int bt = P >> 14;
    const int hw = P & (HW - 1);
    float* outp = out + (size_t)bt * F_ * HW + hw;

    // ---- graph half: load 16 channels x 4 px as pixel-pair packs ----
    {
        ull a01[CG], a23[CG];
        const float4* ip = (const float4*)&g_interp[(size_t)P * CG];
#pragma unroll
        for (int k = 0; k < 4; k++) {
            float4 v0 = ip[k];        // px0, channels 4k..4k+3
            float4 v1 = ip[4 + k];    // px1
            float4 v2 = ip[8 + k];    // px2
            float4 v3 = ip[12 + k];   // px3
            PACK2(a01[4*k+0], v0.x, v1.x); PACK2(a23[4*k+0], v2.x, v3.x);
            PACK2(a01[4*k+1], v0.y, v1.y); PACK2(a23[4*k+1], v2.y, v3.y);
            PACK2(a01[4*k+2], v0.z, v1.z); PACK2(a23[4*k+2], v2.z, v3.z);
            PACK2(a01[4*k+3], v0.w, v1.w); PACK2(a23[4*k+3], v2.w, v3.w);
        }

#pragma unroll 4
        for (int f = 0; f < 32; f++) {
            ull acc01 = s_fg[f], acc23 = s_fg[f];
            const ulonglong2* wrow = (const ulonglong2*)&s_wg[f * 16];
#pragma unroll
            for (int cc = 0; cc < 8; cc++) {
                ulonglong2 w = wrow[cc];          // uniform -> broadcast
                FMA2(acc01, a01[2*cc],   w.x, acc01);
                FMA2(acc23, a23[2*cc],   w.x, acc23);
                FMA2(acc01, a01[2*cc+1], w.y, acc01);
                FMA2(acc23, a23[2*cc+1], w.y, acc23);
            }
            float4 o;
            UNPACK2(o.x, o.y, acc01);
            UNPACK2(o.z, o.w, acc23);
            *(float4*)&outp[(size_t)f * HW] = o;  // coalesced STG.128
        }
    }

    // ---- grid half: 8 channels x 4 px ----
    {
        ull g01[CI], g23[CI];
        const float* gp = &grid_data[(size_t)bt * CI * HW + hw];
#pragma unroll
        for (int c = 0; c < CI; c++) {
            float4 v = *(const float4*)&gp[(size_t)c * HW];  // 4 px of channel c
            PACK2(g01[c], v.x, v.y);
            PACK2(g23[c], v.z, v.w);
        }

#pragma unroll 4
        for (int f = 0; f < 32; f++) {
            ull acc01 = s_fr[f], acc23 = s_fr[f];
            const ulonglong2* wrow = (const ulonglong2*)&s_wr[f * 8];
#pragma unroll
            for (int cc = 0; cc < 4; cc++) {
                ulonglong2 w = wrow[cc];
                FMA2(acc01, g01[2*cc],   w.x, acc01);
                FMA2(acc23, g23[2*cc],   w.x, acc23);
                FMA2(acc01, g01[2*cc+1], w.y, acc01);
                FMA2(acc23, g23[2*cc+1], w.y, acc23);
            }
            float4 o;
            UNPACK2(o.x, o.y, acc01);
            UNPACK2(o.z, o.w, acc23);
            *(float4*)&outp[(size_t)(32 + f) * HW] = o;
        }
    }
}

extern "C" void kernel_launch(void* const* d_in, const int* in_sizes, int n_in,
                              void* d_out, int out_size) {
    (void)in_sizes; (void)n_in; (void)out_size;
    const float* graph  = (const float*)d_in[0];
    const float* grid   = (const float*)d_in[1];
    const float* coords = (const float*)d_in[2];
    const float* Wg     = (const float*)d_in[5];
    const float* bg     = (const float*)d_in[6];
    const float* Wr     = (const float*)d_in[7];
    const float* br     = (const float*)d_in[8];
    const float* gamma  = (const float*)d_in[9];
    const float* beta   = (const float*)d_in[10];
    float* out = (float*)d_out;

    k_zero<<<1024, 256>>>();
    k_scatter<<<(B_ * N_ * CG + 255) / 256, 256>>>(graph, coords);
    k_stats<<<NSTAT, 256>>>(grid, Wg, bg, Wr, br);
    k_norm<<<NNORM, NORM_TPB>>>(grid, Wg, bg, Wr, br, gamma, beta, out);
}